// round 13
// baseline (speedup 1.0000x reference)
#include <cuda_runtime.h>
#include <cuda_fp16.h>
#include <math.h>
#include <stdint.h>

#define G 256
#define BATCH 4
#define SEQ 4096
#define DIM 1024
#define HID 2048      // H
#define HID2 4096     // 2H
#define QD 128
#define ROWS (BATCH*SEQ)   // 16384
#define NGROUP (ROWS/G)    // 64

// ======================= fp32 scratch =======================================
__device__ float g_linkv4[(size_t)16*QD*HID];       // lin_kv split-K partials
__device__ float g_attn[(size_t)NGROUP*G*G];        // fallback if out too small
__device__ float g_bias[G*G];
__device__ float g_bqk[2*QD];                       // concat(b_q, b_k)

// ======================= fp16 planes ========================================
__device__ __align__(16) __half g_hidH[(size_t)ROWS*HID2];                   // hid (vv | gate)
__device__ __align__(16) __half g_nH[(size_t)ROWS*DIM];                      // A: LN(v)
__device__ __align__(16) __half g_qkIn[(size_t)2*ROWS*DIM];                  // A: q | k
__device__ __align__(16) __half g_whTh[(size_t)HID2*DIM];                    // B: w_hid^T (h)
__device__ __align__(16) __half g_woTh[(size_t)DIM*HID];                     // B: w_out^T (h)
__device__ __align__(16) __half g_wqkTh[(size_t)2*QD*DIM], g_wqkTl[(size_t)2*QD*DIM]; // B: wq|wk
__device__ __align__(16) __half g_quadH[(size_t)2*ROWS*QD], g_quadL[(size_t)2*ROWS*QD];
__device__ __align__(16) __half g_linH[(size_t)2*ROWS*QD];                   // lq | lk
__device__ __align__(16) __half g_atH[(size_t)NGROUP*G*G];                   // A: attn
__device__ __align__(16) __half g_lkTH[(size_t)BATCH*QD*SEQ];                // A: lk^T
__device__ __align__(16) __half g_vvTh[(size_t)BATCH*HID*SEQ];               // B: vv^T (h)
__device__ __align__(16) __half g_kvTh[(size_t)BATCH*HID*QD],  g_kvTl[(size_t)BATCH*HID*QD];
__device__ __align__(16) __half g_acH0[(size_t)ROWS*HID];                    // quad_out fp16
__device__ __align__(16) __half g_acH[(size_t)ROWS*HID];                     // gated

// ======================= helpers ============================================
__device__ __forceinline__ uint32_t smem_u32(const void* p) {
    uint32_t a;
    asm("{ .reg .u64 t; cvta.to.shared.u64 t, %1; cvt.u32.u64 %0, t; }" : "=r"(a) : "l"(p));
    return a;
}
__device__ __forceinline__ uint32_t lds32(uint32_t a) {
    uint32_t v;
    asm("ld.shared.b32 %0, [%1];" : "=r"(v) : "r"(a));
    return v;
}
__device__ __forceinline__ void split2h(float x, __half& h, __half& l) {
    h = __float2half_rn(x);
    l = __float2half_rn(x - __half2float(h));
}
__device__ __forceinline__ float silu_f(float x) {
    return x / (1.f + __expf(-x));
}

#define MMA_F16(d, a, b) \
    asm volatile("mma.sync.aligned.m16n8k16.row.col.f32.f16.f16.f32 " \
        "{%0,%1,%2,%3}, {%4,%5,%6,%7}, {%8,%9}, {%0,%1,%2,%3};" \
        : "+f"((d)[0]), "+f"((d)[1]), "+f"((d)[2]), "+f"((d)[3]) \
        : "r"((a)[0]), "r"((a)[1]), "r"((a)[2]), "r"((a)[3]), \
          "r"((b)[0]), "r"((b)[1]))

// fp16-accumulate variant (d = 2 b32 regs holding 4 halves)
#define MMA_F16H(d, a, b) \
    asm volatile("mma.sync.aligned.m16n8k16.row.col.f16.f16.f16.f16 " \
        "{%0,%1}, {%2,%3,%4,%5}, {%6,%7}, {%0,%1};" \
        : "+r"((d)[0]), "+r"((d)[1]) \
        : "r"((a)[0]), "r"((a)[1]), "r"((a)[2]), "r"((a)[3]), \
          "r"((b)[0]), "r"((b)[1]))

// ======================= fp16 multi-product GEMM ============================
// NP=1: C = Ah@Bh^T; NP=2: += Ah@Bl^T; NP=3: += Al@Bh^T   (fp32 accum)
// A16 (NP==1 only): fp16 accumulate within each K=64 chunk, fp32 drain per chunk.
// EPI: 0  C fp32 = v (+ col bias)
//      2  sim: +bias2d, relu^2 -> fp32 C + fp16 O1h
//      3  O1h = (v + Ch) * gate      (all fp16)
//      4  O1h = v                    (fp16)
//      5  O1h = silu(v + col bias)   (fp16)
//      6  proj+affine (q/k select by z)
#define PITCH 144                     // bytes per smem row (64 fp16 + 8 pad)
#define PLANE_A (128*PITCH)           // 18432 B

template<int RP, int NT>
__device__ __forceinline__ void load_plane(uint32_t sdst, const __half* src,
                                           int row0, int ld, int k0, int tid)
{
#pragma unroll
    for (int i = 0; i < RP*8/NT; i++) {
        int idx = tid + i * NT;
        int r = idx >> 3, seg = idx & 7;
        uint32_t d = sdst + r * PITCH + seg * 16;
        const void* gp = src + (size_t)(row0 + r) * ld + k0 + seg * 8;
        asm volatile("cp.async.cg.shared.global [%0], [%1], 16;" :: "r"(d), "l"(gp));
    }
}

template<int TN, int EPI, int NP, bool A16>
__global__ void __launch_bounds__(TN == 256 ? 512 : 256, 1) hgemm(
    const __half* __restrict__ Ah, const __half* __restrict__ Al,
    const __half* __restrict__ Bh, const __half* __restrict__ Bl,
    float* __restrict__ C, const __half* __restrict__ Ch,
    const float* __restrict__ bias, int biasStride,
    const __half* __restrict__ gate, int ldg, long long sG,
    __half* __restrict__ O1h, __half* __restrict__ O1l, __half* __restrict__ O2h,
    const float* __restrict__ gbQ, const float* __restrict__ gbQb,
    const float* __restrict__ gbK, const float* __restrict__ gbKb,
    int K, int lda, int ldb, int ldc,
    long long sA, long long sAi, long long sBo, long long sBi, int zdiv,
    long long sC, float alpha)
{
    constexpr int NT = (TN == 256) ? 512 : 256;
    constexpr int NA = (NP == 3) ? 2 : 1;
    constexpr int NB = (NP >= 2) ? 2 : 1;
    constexpr int PLANE_B = TN * PITCH;
    constexpr int B_OFF = NA * PLANE_A;
    constexpr int STG = NA * PLANE_A + NB * PLANE_B;

    extern __shared__ char smem[];
    const int z = blockIdx.z;
    const int zo = z / zdiv, zi = z - zo * zdiv;
    long long ao = (long long)zo * sA + (long long)zi * sAi;
    long long bo = (long long)zo * sBo + (long long)zi * sBi;
    Ah += ao;
    if (NA == 2) Al += ao;
    Bh += bo;
    if (NB == 2) Bl += bo;
    if (C) C += (long long)z * sC;
    if (bias) bias += (long long)z * biasStride;
    const int bm = blockIdx.y * 128, bn = blockIdx.x * TN;

    const uint32_t sb = smem_u32(smem);
    const int tid = threadIdx.x;
    const int lane = tid & 31, wid = tid >> 5;
    const int warp_m = wid & 3, warp_n = wid >> 2;    // 4 x (TN/64) warps
    const int gr = lane >> 2, tq = lane & 3;

    float acc[2][8][4];
#pragma unroll
    for (int mt = 0; mt < 2; mt++)
#pragma unroll
        for (int nt = 0; nt < 8; nt++)
#pragma unroll
            for (int i = 0; i < 4; i++) acc[mt][nt][i] = 0.f;

    const int nchunks = K >> 6;

    load_plane<128, NT>(sb, Ah, bm, lda, 0, tid);
    if (NA == 2) load_plane<128, NT>(sb + PLANE_A, Al, bm, lda, 0, tid);
    load_plane<TN, NT>(sb + B_OFF, Bh, bn, ldb, 0, tid);
    if (NB == 2) load_plane<TN, NT>(sb + B_OFF + PLANE_B, Bl, bn, ldb, 0, tid);
    asm volatile("cp.async.commit_group;");

    for (int c = 0; c < nchunks; ++c) {
        if (c + 1 < nchunks) {
            uint32_t st = sb + ((c + 1) & 1) * STG;
            int k0 = (c + 1) << 6;
            load_plane<128, NT>(st, Ah, bm, lda, k0, tid);
            if (NA == 2) load_plane<128, NT>(st + PLANE_A, Al, bm, lda, k0, tid);
            load_plane<TN, NT>(st + B_OFF, Bh, bn, ldb, k0, tid);
            if (NB == 2) load_plane<TN, NT>(st + B_OFF + PLANE_B, Bl, bn, ldb, k0, tid);
            asm volatile("cp.async.commit_group;");
            asm volatile("cp.async.wait_group %0;" :: "n"(1));
        } else {
            asm volatile("cp.async.wait_group %0;" :: "n"(0));
        }
        __syncthreads();

        const uint32_t stg = sb + (c & 1) * STG;

        uint32_t acc16[2][8][2];
        if (A16) {
#pragma unroll
            for (int mt = 0; mt < 2; mt++)
#pragma unroll
                for (int nt = 0; nt < 8; nt++) {
                    acc16[mt][nt][0] = 0u;
                    acc16[mt][nt][1] = 0u;
                }
        }

#pragma unroll
        for (int kk = 0; kk < 4; kk++) {
            const int koff = kk * 32;
            uint32_t a_h[2][4], a_l[2][4];
#pragma unroll
            for (int mt = 0; mt < 2; mt++) {
                uint32_t ro = stg + (warp_m*32 + mt*16 + gr) * PITCH + koff + tq*4;
                a_h[mt][0] = lds32(ro);
                a_h[mt][1] = lds32(ro + 8*PITCH);
                a_h[mt][2] = lds32(ro + 16);
                a_h[mt][3] = lds32(ro + 8*PITCH + 16);
                if (NA == 2) {
                    uint32_t rl = ro + PLANE_A;
                    a_l[mt][0] = lds32(rl);
                    a_l[mt][1] = lds32(rl + 8*PITCH);
                    a_l[mt][2] = lds32(rl + 16);
                    a_l[mt][3] = lds32(rl + 8*PITCH + 16);
                }
            }
#pragma unroll
            for (int nt = 0; nt < 8; nt++) {
                uint32_t ro = stg + B_OFF + (warp_n*64 + nt*8 + gr) * PITCH + koff + tq*4;
                uint32_t b_h[2], b_l[2];
                b_h[0] = lds32(ro);
                b_h[1] = lds32(ro + 16);
                if (NB == 2) {
                    b_l[0] = lds32(ro + PLANE_B);
                    b_l[1] = lds32(ro + PLANE_B + 16);
                }
#pragma unroll
                for (int mt = 0; mt < 2; mt++) {
                    if (A16) {
                        MMA_F16H(acc16[mt][nt], a_h[mt], b_h);
                    } else {
                        MMA_F16(acc[mt][nt], a_h[mt], b_h);
                        if (NP >= 2) MMA_F16(acc[mt][nt], a_h[mt], b_l);
                        if (NP == 3) MMA_F16(acc[mt][nt], a_l[mt], b_h);
                    }
                }
            }
        }

        if (A16) {
            // drain fp16 chunk accumulators into fp32
#pragma unroll
            for (int mt = 0; mt < 2; mt++)
#pragma unroll
                for (int nt = 0; nt < 8; nt++) {
                    __half2 lo = *reinterpret_cast<__half2*>(&acc16[mt][nt][0]);
                    __half2 hi = *reinterpret_cast<__half2*>(&acc16[mt][nt][1]);
                    float2 flo = __half22float2(lo);
                    float2 fhi = __half22float2(hi);
                    acc[mt][nt][0] += flo.x;
                    acc[mt][nt][1] += flo.y;
                    acc[mt][nt][2] += fhi.x;
                    acc[mt][nt][3] += fhi.y;
                }
        }
        __syncthreads();
    }

    // epilogue
    const float* gbG = (EPI == 6) ? (z ? gbK : gbQ) : nullptr;
    const float* gbB = (EPI == 6) ? (z ? gbKb : gbQb) : nullptr;
#pragma unroll
    for (int mt = 0; mt < 2; mt++) {
        const int row0 = bm + warp_m*32 + mt*16 + gr;
#pragma unroll
        for (int nt = 0; nt < 8; nt++) {
            const int col = bn + warp_n*64 + nt*8 + tq*2;
            float2 bb = make_float2(0.f, 0.f);
            if ((EPI == 0 || EPI == 5 || EPI == 6) && bias)
                bb = *reinterpret_cast<const float2*>(bias + col);
#pragma unroll
            for (int h = 0; h < 2; h++) {
                const int row = row0 + h*8;
                float vx = acc[mt][nt][h*2+0] * alpha;
                float vy = acc[mt][nt][h*2+1] * alpha;
                const size_t idx = (size_t)row * ldc + col;
                const size_t zidx = (long long)z * sC + idx;
                if (EPI == 0) {
                    *reinterpret_cast<float2*>(C + idx) = make_float2(vx + bb.x, vy + bb.y);
                } else if (EPI == 2) {
                    float2 b2 = *reinterpret_cast<const float2*>(bias + (size_t)row * G + col);
                    vx += b2.x; vy += b2.y;
                    vx = fmaxf(vx, 0.f); vy = fmaxf(vy, 0.f);
                    vx *= vx; vy *= vy;
                    *reinterpret_cast<float2*>(C + idx) = make_float2(vx, vy);
                    *reinterpret_cast<__half2*>(O1h + zidx) = __floats2half2_rn(vx, vy);
                } else if (EPI == 3) {
                    __half2 o2 = *reinterpret_cast<const __half2*>(Ch + zidx);
                    float2 o = __half22float2(o2);
                    __half2 g2h = *reinterpret_cast<const __half2*>(
                        gate + (long long)z * sG + (size_t)row * ldg + col);
                    float2 g2 = __half22float2(g2h);
                    vx = (vx + o.x) * g2.x;
                    vy = (vy + o.y) * g2.y;
                    *reinterpret_cast<__half2*>(O1h + zidx) = __floats2half2_rn(vx, vy);
                } else if (EPI == 4) {
                    *reinterpret_cast<__half2*>(O1h + zidx) = __floats2half2_rn(vx, vy);
                } else if (EPI == 5) {
                    vx = silu_f(vx + bb.x);
                    vy = silu_f(vy + bb.y);
                    *reinterpret_cast<__half2*>(O1h + idx) = __floats2half2_rn(vx, vy);
                } else if (EPI == 6) {
                    float sx = silu_f(vx + bb.x);
                    float sy = silu_f(vy + bb.y);
                    float2 gq = *reinterpret_cast<const float2*>(gbG + col);
                    float2 bq2 = *reinterpret_cast<const float2*>(gbB + col);
                    float2 gl = *reinterpret_cast<const float2*>(gbG + QD + col);
                    float2 bl2 = *reinterpret_cast<const float2*>(gbB + QD + col);
                    float qx = sx * gq.x + bq2.x, qy = sy * gq.y + bq2.y;
                    __half hx, lx, hy, ly;
                    split2h(qx, hx, lx); split2h(qy, hy, ly);
                    *reinterpret_cast<__half2*>(O1h + zidx) = __halves2half2(hx, hy);
                    *reinterpret_cast<__half2*>(O1l + zidx) = __halves2half2(lx, ly);
                    float lxv = sx * gl.x + bl2.x, lyv = sy * gl.y + bl2.y;
                    *reinterpret_cast<__half2*>(O2h + zidx) = __floats2half2_rn(lxv, lyv);
                }
            }
        }
    }
}

// ======================= elementwise / transform kernels ====================
__global__ void ln_kernel(const float* __restrict__ v, const float* __restrict__ g,
                          const float* __restrict__ b, __half* __restrict__ oh)
{
    int row = blockIdx.x;
    const float4* x4 = reinterpret_cast<const float4*>(v + (size_t)row * DIM);
    int t = threadIdx.x;
    float4 a = x4[t];
    float s = a.x + a.y + a.z + a.w;
    __shared__ float red[256];
    red[t] = s; __syncthreads();
    for (int o = 128; o > 0; o >>= 1) { if (t < o) red[t] += red[t+o]; __syncthreads(); }
    float mu = red[0] * (1.f/DIM);
    __syncthreads();
    float dx = a.x-mu, dy = a.y-mu, dz = a.z-mu, dw = a.w-mu;
    red[t] = dx*dx + dy*dy + dz*dz + dw*dw; __syncthreads();
    for (int o = 128; o > 0; o >>= 1) { if (t < o) red[t] += red[t+o]; __syncthreads(); }
    float inv = rsqrtf(red[0] * (1.f/DIM) + 1e-5f);
    float4 g4 = reinterpret_cast<const float4*>(g)[t];
    float4 b4 = reinterpret_cast<const float4*>(b)[t];
    __half2 h0 = __floats2half2_rn(dx*inv*g4.x + b4.x, dy*inv*g4.y + b4.y);
    __half2 h1 = __floats2half2_rn(dz*inv*g4.z + b4.z, dw*inv*g4.w + b4.w);
    reinterpret_cast<uint2*>(oh + (size_t)row * DIM)[t] =
        make_uint2(*reinterpret_cast<uint32_t*>(&h0), *reinterpret_cast<uint32_t*>(&h1));
}

__global__ void bias_kernel(const float* __restrict__ rel_emb, float* __restrict__ bias)
{
    int idx = blockIdx.x * 256 + threadIdx.x;
    int i = idx >> 8, j = idx & 255;
    int n0 = i - j;
    int ret = (n0 < 0) ? 16 : 0;
    int n = n0 < 0 ? -n0 : n0;
    int bucket;
    if (n < 8) bucket = ret + n;
    else {
        int vl = 8 + (int)(logf((float)n * 0.125f) / 2.7725887f * 8.0f);
        if (vl > 15) vl = 15;
        bucket = ret + vl;
    }
    bias[idx] = rel_emb[bucket] * 11.3137085f;
}

__global__ void bcat_kernel(const float* __restrict__ bq, const float* __restrict__ bk,
                            float* __restrict__ o)
{
    int t = threadIdx.x;
    o[t] = (t < QD) ? bq[t] : bk[t - QD];
}

__global__ void cvt4(const float* __restrict__ in, __half* __restrict__ oh)
{
    size_t i = (size_t)blockIdx.x * 256 + threadIdx.x;
    float4 a = reinterpret_cast<const float4*>(in)[i];
    __half2 h0 = __floats2half2_rn(a.x, a.y);
    __half2 h1 = __floats2half2_rn(a.z, a.w);
    reinterpret_cast<uint2*>(oh)[i] =
        make_uint2(*reinterpret_cast<uint32_t*>(&h0), *reinterpret_cast<uint32_t*>(&h1));
}

// transpose fp32 [R, C] -> fp16 [C, R]; ol == nullptr -> h only
__global__ void transcvt(const float* __restrict__ in,
                         __half* __restrict__ oh, __half* __restrict__ ol,
                         int ld_in, int ld_out, long long sIn, long long sOut)
{
    __shared__ float t[32][33];
    in += (long long)blockIdx.z * sIn;
    oh += (long long)blockIdx.z * sOut;
    if (ol) ol += (long long)blockIdx.z * sOut;
    int c0 = blockIdx.x * 32, r0 = blockIdx.y * 32;
    int tx = threadIdx.x, ty = threadIdx.y;
#pragma unroll
    for (int i = 0; i < 4; i++)
        t[ty + i*8][tx] = in[(size_t)(r0 + ty + i*8) * ld_in + c0 + tx];
    __syncthreads();
#pragma unroll
    for (int i = 0; i < 4; i++) {
        float x = t[tx][ty + i*8];
        size_t o = (size_t)(c0 + ty + i*8) * ld_out + r0 + tx;
        __half h, l; split2h(x, h, l);
        oh[o] = h;
        if (ol) ol[o] = l;
    }
}

// pure fp16 transpose [R, C] -> [C, R]
__global__ void trans16(const __half* __restrict__ in, __half* __restrict__ out,
                        int ld_in, int ld_out, long long sIn, long long sOut)
{
    __shared__ __half t[32][34];
    in += (long long)blockIdx.z * sIn;
    out += (long long)blockIdx.z * sOut;
    int c0 = blockIdx.x * 32, r0 = blockIdx.y * 32;
    int tx = threadIdx.x, ty = threadIdx.y;
#pragma unroll
    for (int i = 0; i < 4; i++)
        t[ty + i*8][tx] = in[(size_t)(r0 + ty + i*8) * ld_in + c0 + tx];
    __syncthreads();
#pragma unroll
    for (int i = 0; i < 4; i++)
        out[(size_t)(c0 + ty + i*8) * ld_out + r0 + tx] = t[tx][ty + i*8];
}

// sum 4 split-K partials [4][QD][HID] per batch, transpose -> kvT [HID][QD] (h+l)
__global__ void kvsum_t(const float* __restrict__ linkv4,
                        __half* __restrict__ kvh, __half* __restrict__ kvl)
{
    __shared__ float t[32][33];
    int batch = blockIdx.z;
    const float* base = linkv4 + (size_t)batch * 4 * QD * HID;
    kvh += (size_t)batch * HID * QD;
    kvl += (size_t)batch * HID * QD;
    int c0 = blockIdx.x * 32, r0 = blockIdx.y * 32;
    int tx = threadIdx.x, ty = threadIdx.y;
#pragma unroll
    for (int i = 0; i < 4; i++) {
        size_t off = (size_t)(r0 + ty + i*8) * HID + c0 + tx;
        float s = base[off] + base[off + (size_t)QD*HID]
                + base[off + (size_t)2*QD*HID] + base[off + (size_t)3*QD*HID];
        t[ty + i*8][tx] = s;
    }
    __syncthreads();
#pragma unroll
    for (int i = 0; i < 4; i++) {
        float x = t[tx][ty + i*8];
        size_t o = (size_t)(c0 + ty + i*8) * QD + r0 + tx;
        __half h, l; split2h(x, h, l);
        kvh[o] = h; kvl[o] = l;
    }
}

// ======================= host orchestration =================================
static void* symaddr(const void* s) {
    void* p = nullptr;
    cudaGetSymbolAddress(&p, s);
    return p;
}

extern "C" void kernel_launch(void* const* d_in, const int* in_sizes, int n_in,
                              void* d_out, int out_size)
{
    const float* q       = (const float*)d_in[0];
    const float* k       = (const float*)d_in[1];
    const float* v       = (const float*)d_in[2];
    const float* ln_g    = (const float*)d_in[3];
    const float* ln_b    = (const float*)d_in[4];
    const float* w_hid   = (const float*)d_in[5];
    const float* b_hid   = (const float*)d_in[6];
    const float* w_q     = (const float*)d_in[7];
    const float* b_q     = (const float*)d_in[8];
    const float* w_k     = (const float*)d_in[9];
    const float* b_k     = (const float*)d_in[10];
    const float* qs_gamma= (const float*)d_in[11];
    const float* qs_beta = (const float*)d_in[12];
    const float* ks_gamma= (const float*)d_in[13];
    const float* ks_beta = (const float*)d_in[14];
    const float* rel_emb = (const float*)d_in[15];
    const float* w_out   = (const float*)d_in[16];
    const float* b_out   = (const float*)d_in[17];

    float* out = (float*)d_out;

    float* linkv4 = (float*)symaddr(g_linkv4);
    float* biasbuf= (float*)symaddr(g_bias);
    float* bqk    = (float*)symaddr(g_bqk);
    float* attn_scratch = (float*)symaddr(g_attn);

    __half* hidH  = (__half*)symaddr(g_hidH);
    __half* nH    = (__half*)symaddr(g_nH);
    __half* qkIn  = (__half*)symaddr(g_qkIn);
    __half* whTh  = (__half*)symaddr(g_whTh);
    __half* woTh  = (__half*)symaddr(g_woTh);
    __half* wqkTh = (__half*)symaddr(g_wqkTh); __half* wqkTl = (__half*)symaddr(g_wqkTl);
    __half* quadH = (__half*)symaddr(g_quadH); __half* quadL = (__half*)symaddr(g_quadL);
    __half* linH  = (__half*)symaddr(g_linH);
    __half* atH   = (__half*)symaddr(g_atH);
    __half* lkTH  = (__half*)symaddr(g_lkTH);
    __half* vvTh  = (__half*)symaddr(g_vvTh);
    __half* kvTh  = (__half*)symaddr(g_kvTh);  __half* kvTl  = (__half*)symaddr(g_kvTl);
    __half* acH0  = (__half*)symaddr(g_acH0);
    __half* acH   = (__half*)symaddr(g_acH);

    const long long OUT0 = (long long)ROWS * DIM;
    const long long OUT1 = (long long)NGROUP * G * G;
    float* attn = (out_size >= OUT0 + OUT1) ? (out + OUT0) : attn_scratch;

    const long long RQ = (long long)ROWS * QD;

    cudaFuncSetAttribute(hgemm<256,5,1,true >, cudaFuncAttributeMaxDynamicSharedMemorySize, 110592);
    cudaFuncSetAttribute(hgemm<128,6,2,false>, cudaFuncAttributeMaxDynamicSharedMemorySize, 110592);
    cudaFuncSetAttribute(hgemm<128,2,3,false>, cudaFuncAttributeMaxDynamicSharedMemorySize, 147456);
    cudaFuncSetAttribute(hgemm<256,4,1,false>, cudaFuncAttributeMaxDynamicSharedMemorySize, 110592);
    cudaFuncSetAttribute(hgemm<256,0,1,false>, cudaFuncAttributeMaxDynamicSharedMemorySize, 110592);
    cudaFuncSetAttribute(hgemm<256,0,1,true >, cudaFuncAttributeMaxDynamicSharedMemorySize, 110592);
    cudaFuncSetAttribute(hgemm<256,3,2,false>, cudaFuncAttributeMaxDynamicSharedMemorySize, 184320);

    ln_kernel<<<ROWS, 256>>>(v, ln_g, ln_b, nH);
    transcvt<<<dim3(HID2/32, DIM/32, 1), dim3(32,8)>>>(w_hid, whTh, nullptr, HID2, DIM, 0, 0);
    bias_kernel<<<G*G/256, 256>>>(rel_emb, biasbuf);
    cvt4<<<(int)((size_t)ROWS*DIM/1024), 256>>>(q, qkIn);
    cvt4<<<(int)((size_t)ROWS*DIM/1024), 256>>>(k, qkIn + (size_t)ROWS*DIM);

    // hid = silu(normed @ w_hid + b_hid) -> fp16 hidH  [fp16-accum experiment]
    hgemm<256,5,1,true><<<dim3(HID2/256, ROWS/128, 1), 512, 110592>>>(
        nH, nullptr, whTh, nullptr, nullptr, nullptr, b_hid, 0, nullptr, 0, 0,
        hidH, nullptr, nullptr, nullptr, nullptr, nullptr, nullptr,
        DIM, DIM, DIM, HID2, 0, 0, 0, 0, 1, 0, 1.f);

    transcvt<<<dim3(DIM/32, HID/32, 1), dim3(32,8)>>>(w_out, woTh, nullptr, DIM, HID, 0, 0);
    transcvt<<<dim3(QD/32, DIM/32, 1), dim3(32,8)>>>(w_q, wqkTh, wqkTl, QD, DIM, 0, 0);
    transcvt<<<dim3(QD/32, DIM/32, 1), dim3(32,8)>>>(w_k, wqkTh + QD*DIM, wqkTl + QD*DIM, QD, DIM, 0, 0);
    bcat_kernel<<<1, 2*QD>>>(b_q, b_k, bqk);

    // fused projection + affine (z=0: q -> qq,lq; z=1: k -> qk,lk), 2 products
    hgemm<128,6,2,false><<<dim3(1, ROWS/128, 2), 256, 110592>>>(
        qkIn, nullptr, wqkTh, wqkTl, nullptr, nullptr, bqk, QD, nullptr, 0, 0,
        quadH, quadL, linH, qs_gamma, qs_beta, ks_gamma, ks_beta,
        DIM, DIM, DIM, QD,
        (long long)ROWS*DIM, 0, (long long)QD*DIM, 0, 1, RQ, 1.f);

    // sim: attn = relu(qq@qk^T / G + bias)^2 — 3 products (checked output)
    hgemm<128,2,3,false><<<dim3(G/128, G/128, NGROUP), 256, 147456>>>(
        quadH, quadL, quadH + RQ, quadL + RQ, attn, nullptr, biasbuf, 0, nullptr, 0, 0,
        atH, nullptr, nullptr, nullptr, nullptr, nullptr, nullptr,
        QD, QD, QD, G,
        (long long)G*QD, 0, (long long)G*QD, 0, 1, (long long)G*G, 1.f/G);

    // vv^T: hidH[:, :2048] per batch -> [4][2048][4096]
    trans16<<<dim3(HID/32, SEQ/32, BATCH), dim3(32,8)>>>(
        hidH, vvTh, HID2, SEQ, (long long)SEQ*HID2, (long long)HID*SEQ);

    // quad_out = attn @ cv -> fp16 acH0
    hgemm<256,4,1,false><<<dim3(HID/256, G/128, NGROUP), 512, 110592>>>(
        atH, nullptr, vvTh, nullptr, nullptr, nullptr, nullptr, 0, nullptr, 0, 0,
        acH0, nullptr, nullptr, nullptr, nullptr, nullptr, nullptr,
        G, G, SEQ, HID,
        (long long)16*G*G, (long long)G*G, (long long)HID*SEQ, (long long)G, 16,
        (long long)G*HID, 1.f);

    // lk^T: [4][4096][128] -> [4][128][4096]
    trans16<<<dim3(QD/32, SEQ/32, BATCH), dim3(32,8)>>>(
        linH + RQ, lkTH, QD, SEQ, (long long)SEQ*QD, (long long)QD*SEQ);

    // lin_kv split-K 4x -> linkv4[16]
    hgemm<256,0,1,false><<<dim3(HID/256, 1, 16), 512, 110592>>>(
        lkTH, nullptr, vvTh, nullptr, linkv4, nullptr, nullptr, 0, nullptr, 0, 0,
        nullptr, nullptr, nullptr, nullptr, nullptr, nullptr, nullptr,
        1024, SEQ, SEQ, HID,
        (long long)QD*SEQ, 1024LL, (long long)HID*SEQ, 1024LL, 4,
        (long long)QD*HID, 1.f/SEQ);

    // sum partials + transpose -> kvT planes [4][2048][128] (h+l)
    kvsum_t<<<dim3(HID/32, QD/32, BATCH), dim3(32,8)>>>(linkv4, kvTh, kvTl);

    // lin_out fused: acH = (lq @ lin_kv + acH0) * gate — 2 products
    hgemm<256,3,2,false><<<dim3(HID/256, SEQ/128, BATCH), 512, 184320>>>(
        linH, nullptr, kvTh, kvTl, nullptr, acH0, nullptr, 0,
        hidH + HID, HID2, (long long)SEQ*HID2,
        acH, nullptr, nullptr, nullptr, nullptr, nullptr, nullptr,
        QD, QD, QD, HID,
        (long long)SEQ*QD, 0, (long long)HID*QD, 0, 1, (long long)SEQ*HID, 1.f);

    // out = gated @ w_out + b_out  [fp16-accum experiment]
    hgemm<256,0,1,true><<<dim3(DIM/256, ROWS/128, 1), 512, 110592>>>(
        acH, nullptr, woTh, nullptr, out, nullptr, b_out, 0, nullptr, 0, 0,
        nullptr, nullptr, nullptr, nullptr, nullptr, nullptr, nullptr,
        HID, HID, HID, DIM, 0, 0, 0, 0, 1, 0, 1.f);
}

// round 14
// speedup vs baseline: 1.1438x; 1.1438x over previous
#include <cuda_runtime.h>
#include <cuda_fp16.h>
#include <math.h>
#include <stdint.h>

#define G 256
#define BATCH 4
#define SEQ 4096
#define DIM 1024
#define HID 2048      // H
#define HID2 4096     // 2H
#define QD 128
#define ROWS (BATCH*SEQ)   // 16384
#define NGROUP (ROWS/G)    // 64

// ======================= fp32 scratch =======================================
__device__ float g_linkv4[(size_t)16*QD*HID];       // lin_kv split-K partials
__device__ float g_attn[(size_t)NGROUP*G*G];        // fallback if out too small
__device__ float g_bias[G*G];
__device__ float g_bqk[2*QD];                       // concat(b_q, b_k)

// ======================= fp16 planes ========================================
__device__ __align__(16) __half g_hidH[(size_t)ROWS*HID2];                   // hid (vv | gate)
__device__ __align__(16) __half g_nH[(size_t)ROWS*DIM];                      // A: LN(v)
__device__ __align__(16) __half g_qkIn[(size_t)2*ROWS*DIM];                  // A: q | k
__device__ __align__(16) __half g_whTh[(size_t)HID2*DIM];                    // B: w_hid^T (h)
__device__ __align__(16) __half g_woTh[(size_t)DIM*HID];                     // B: w_out^T (h)
__device__ __align__(16) __half g_wqkTh[(size_t)2*QD*DIM], g_wqkTl[(size_t)2*QD*DIM]; // B: wq|wk
__device__ __align__(16) __half g_quadH[(size_t)2*ROWS*QD], g_quadL[(size_t)2*ROWS*QD];
__device__ __align__(16) __half g_linH[(size_t)2*ROWS*QD];                   // lq | lk
__device__ __align__(16) __half g_atH[(size_t)NGROUP*G*G];                   // A: attn
__device__ __align__(16) __half g_lkTH[(size_t)BATCH*QD*SEQ];                // A: lk^T
__device__ __align__(16) __half g_vvTh[(size_t)BATCH*HID*SEQ];               // B: vv^T (h)
__device__ __align__(16) __half g_kvTh[(size_t)BATCH*HID*QD];                // B: lin_kv^T (h)
__device__ __align__(16) __half g_acH0[(size_t)ROWS*HID];                    // quad_out fp16
__device__ __align__(16) __half g_acH[(size_t)ROWS*HID];                     // gated

// ======================= helpers ============================================
__device__ __forceinline__ uint32_t smem_u32(const void* p) {
    uint32_t a;
    asm("{ .reg .u64 t; cvta.to.shared.u64 t, %1; cvt.u32.u64 %0, t; }" : "=r"(a) : "l"(p));
    return a;
}
__device__ __forceinline__ uint32_t lds32(uint32_t a) {
    uint32_t v;
    asm("ld.shared.b32 %0, [%1];" : "=r"(v) : "r"(a));
    return v;
}
__device__ __forceinline__ void split2h(float x, __half& h, __half& l) {
    h = __float2half_rn(x);
    l = __float2half_rn(x - __half2float(h));
}
__device__ __forceinline__ float silu_f(float x) {
    return x / (1.f + __expf(-x));
}

#define MMA_F16(d, a, b) \
    asm volatile("mma.sync.aligned.m16n8k16.row.col.f32.f16.f16.f32 " \
        "{%0,%1,%2,%3}, {%4,%5,%6,%7}, {%8,%9}, {%0,%1,%2,%3};" \
        : "+f"((d)[0]), "+f"((d)[1]), "+f"((d)[2]), "+f"((d)[3]) \
        : "r"((a)[0]), "r"((a)[1]), "r"((a)[2]), "r"((a)[3]), \
          "r"((b)[0]), "r"((b)[1]))

// ======================= fp16 multi-product GEMM ============================
// NP=1: C = Ah@Bh^T; NP=2: += Ah@Bl^T; NP=3: += Al@Bh^T   (fp32 accum)
// EPI: 0  C fp32 = v (+ col bias)
//      2  sim: +bias2d, relu^2 -> fp32 C + fp16 O1h
//      3  O1h = (v + Ch) * gate      (all fp16)
//      4  O1h = v                    (fp16)
//      5  O1h = silu(v + col bias)   (fp16)
//      6  proj+affine (q/k select by z)
#define PITCH 144                     // bytes per smem row (64 fp16 + 8 pad)
#define PLANE_A (128*PITCH)           // 18432 B

template<int RP, int NT>
__device__ __forceinline__ void load_plane(uint32_t sdst, const __half* src,
                                           int row0, int ld, int k0, int tid)
{
#pragma unroll
    for (int i = 0; i < RP*8/NT; i++) {
        int idx = tid + i * NT;
        int r = idx >> 3, seg = idx & 7;
        uint32_t d = sdst + r * PITCH + seg * 16;
        const void* gp = src + (size_t)(row0 + r) * ld + k0 + seg * 8;
        asm volatile("cp.async.cg.shared.global [%0], [%1], 16;" :: "r"(d), "l"(gp));
    }
}

template<int TN, int EPI, int NP>
__global__ void __launch_bounds__(TN == 256 ? 512 : 256, 1) hgemm(
    const __half* __restrict__ Ah, const __half* __restrict__ Al,
    const __half* __restrict__ Bh, const __half* __restrict__ Bl,
    float* __restrict__ C, const __half* __restrict__ Ch,
    const float* __restrict__ bias, int biasStride,
    const __half* __restrict__ gate, int ldg, long long sG,
    __half* __restrict__ O1h, __half* __restrict__ O1l, __half* __restrict__ O2h,
    const float* __restrict__ gbQ, const float* __restrict__ gbQb,
    const float* __restrict__ gbK, const float* __restrict__ gbKb,
    int K, int lda, int ldb, int ldc,
    long long sA, long long sAi, long long sBo, long long sBi, int zdiv,
    long long sC, float alpha)
{
    constexpr int NT = (TN == 256) ? 512 : 256;
    constexpr int NA = (NP == 3) ? 2 : 1;
    constexpr int NB = (NP >= 2) ? 2 : 1;
    constexpr int PLANE_B = TN * PITCH;
    constexpr int B_OFF = NA * PLANE_A;
    constexpr int STG = NA * PLANE_A + NB * PLANE_B;

    extern __shared__ char smem[];
    const int z = blockIdx.z;
    const int zo = z / zdiv, zi = z - zo * zdiv;
    long long ao = (long long)zo * sA + (long long)zi * sAi;
    long long bo = (long long)zo * sBo + (long long)zi * sBi;
    Ah += ao;
    if (NA == 2) Al += ao;
    Bh += bo;
    if (NB == 2) Bl += bo;
    if (C) C += (long long)z * sC;
    if (bias) bias += (long long)z * biasStride;
    const int bm = blockIdx.y * 128, bn = blockIdx.x * TN;

    const uint32_t sb = smem_u32(smem);
    const int tid = threadIdx.x;
    const int lane = tid & 31, wid = tid >> 5;
    const int warp_m = wid & 3, warp_n = wid >> 2;    // 4 x (TN/64) warps
    const int gr = lane >> 2, tq = lane & 3;

    float acc[2][8][4];
#pragma unroll
    for (int mt = 0; mt < 2; mt++)
#pragma unroll
        for (int nt = 0; nt < 8; nt++)
#pragma unroll
            for (int i = 0; i < 4; i++) acc[mt][nt][i] = 0.f;

    const int nchunks = K >> 6;

    load_plane<128, NT>(sb, Ah, bm, lda, 0, tid);
    if (NA == 2) load_plane<128, NT>(sb + PLANE_A, Al, bm, lda, 0, tid);
    load_plane<TN, NT>(sb + B_OFF, Bh, bn, ldb, 0, tid);
    if (NB == 2) load_plane<TN, NT>(sb + B_OFF + PLANE_B, Bl, bn, ldb, 0, tid);
    asm volatile("cp.async.commit_group;");

    for (int c = 0; c < nchunks; ++c) {
        if (c + 1 < nchunks) {
            uint32_t st = sb + ((c + 1) & 1) * STG;
            int k0 = (c + 1) << 6;
            load_plane<128, NT>(st, Ah, bm, lda, k0, tid);
            if (NA == 2) load_plane<128, NT>(st + PLANE_A, Al, bm, lda, k0, tid);
            load_plane<TN, NT>(st + B_OFF, Bh, bn, ldb, k0, tid);
            if (NB == 2) load_plane<TN, NT>(st + B_OFF + PLANE_B, Bl, bn, ldb, k0, tid);
            asm volatile("cp.async.commit_group;");
            asm volatile("cp.async.wait_group %0;" :: "n"(1));
        } else {
            asm volatile("cp.async.wait_group %0;" :: "n"(0));
        }
        __syncthreads();

        const uint32_t stg = sb + (c & 1) * STG;
#pragma unroll
        for (int kk = 0; kk < 4; kk++) {
            const int koff = kk * 32;
            uint32_t a_h[2][4], a_l[2][4];
#pragma unroll
            for (int mt = 0; mt < 2; mt++) {
                uint32_t ro = stg + (warp_m*32 + mt*16 + gr) * PITCH + koff + tq*4;
                a_h[mt][0] = lds32(ro);
                a_h[mt][1] = lds32(ro + 8*PITCH);
                a_h[mt][2] = lds32(ro + 16);
                a_h[mt][3] = lds32(ro + 8*PITCH + 16);
                if (NA == 2) {
                    uint32_t rl = ro + PLANE_A;
                    a_l[mt][0] = lds32(rl);
                    a_l[mt][1] = lds32(rl + 8*PITCH);
                    a_l[mt][2] = lds32(rl + 16);
                    a_l[mt][3] = lds32(rl + 8*PITCH + 16);
                }
            }
#pragma unroll
            for (int nt = 0; nt < 8; nt++) {
                uint32_t ro = stg + B_OFF + (warp_n*64 + nt*8 + gr) * PITCH + koff + tq*4;
                uint32_t b_h[2], b_l[2];
                b_h[0] = lds32(ro);
                b_h[1] = lds32(ro + 16);
                if (NB == 2) {
                    b_l[0] = lds32(ro + PLANE_B);
                    b_l[1] = lds32(ro + PLANE_B + 16);
                }
#pragma unroll
                for (int mt = 0; mt < 2; mt++) {
                    MMA_F16(acc[mt][nt], a_h[mt], b_h);
                    if (NP >= 2) MMA_F16(acc[mt][nt], a_h[mt], b_l);
                    if (NP == 3) MMA_F16(acc[mt][nt], a_l[mt], b_h);
                }
            }
        }
        __syncthreads();
    }

    // epilogue
    const float* gbG = (EPI == 6) ? (z ? gbK : gbQ) : nullptr;
    const float* gbB = (EPI == 6) ? (z ? gbKb : gbQb) : nullptr;
#pragma unroll
    for (int mt = 0; mt < 2; mt++) {
        const int row0 = bm + warp_m*32 + mt*16 + gr;
#pragma unroll
        for (int nt = 0; nt < 8; nt++) {
            const int col = bn + warp_n*64 + nt*8 + tq*2;
            float2 bb = make_float2(0.f, 0.f);
            if ((EPI == 0 || EPI == 5 || EPI == 6) && bias)
                bb = *reinterpret_cast<const float2*>(bias + col);
#pragma unroll
            for (int h = 0; h < 2; h++) {
                const int row = row0 + h*8;
                float vx = acc[mt][nt][h*2+0] * alpha;
                float vy = acc[mt][nt][h*2+1] * alpha;
                const size_t idx = (size_t)row * ldc + col;
                const size_t zidx = (long long)z * sC + idx;
                if (EPI == 0) {
                    *reinterpret_cast<float2*>(C + idx) = make_float2(vx + bb.x, vy + bb.y);
                } else if (EPI == 2) {
                    float2 b2 = *reinterpret_cast<const float2*>(bias + (size_t)row * G + col);
                    vx += b2.x; vy += b2.y;
                    vx = fmaxf(vx, 0.f); vy = fmaxf(vy, 0.f);
                    vx *= vx; vy *= vy;
                    *reinterpret_cast<float2*>(C + idx) = make_float2(vx, vy);
                    *reinterpret_cast<__half2*>(O1h + zidx) = __floats2half2_rn(vx, vy);
                } else if (EPI == 3) {
                    __half2 o2 = *reinterpret_cast<const __half2*>(Ch + zidx);
                    float2 o = __half22float2(o2);
                    __half2 g2h = *reinterpret_cast<const __half2*>(
                        gate + (long long)z * sG + (size_t)row * ldg + col);
                    float2 g2 = __half22float2(g2h);
                    vx = (vx + o.x) * g2.x;
                    vy = (vy + o.y) * g2.y;
                    *reinterpret_cast<__half2*>(O1h + zidx) = __floats2half2_rn(vx, vy);
                } else if (EPI == 4) {
                    *reinterpret_cast<__half2*>(O1h + zidx) = __floats2half2_rn(vx, vy);
                } else if (EPI == 5) {
                    vx = silu_f(vx + bb.x);
                    vy = silu_f(vy + bb.y);
                    *reinterpret_cast<__half2*>(O1h + idx) = __floats2half2_rn(vx, vy);
                } else if (EPI == 6) {
                    float sx = silu_f(vx + bb.x);
                    float sy = silu_f(vy + bb.y);
                    float2 gq = *reinterpret_cast<const float2*>(gbG + col);
                    float2 bq2 = *reinterpret_cast<const float2*>(gbB + col);
                    float2 gl = *reinterpret_cast<const float2*>(gbG + QD + col);
                    float2 bl2 = *reinterpret_cast<const float2*>(gbB + QD + col);
                    float qx = sx * gq.x + bq2.x, qy = sy * gq.y + bq2.y;
                    __half hx, lx, hy, ly;
                    split2h(qx, hx, lx); split2h(qy, hy, ly);
                    *reinterpret_cast<__half2*>(O1h + zidx) = __halves2half2(hx, hy);
                    *reinterpret_cast<__half2*>(O1l + zidx) = __halves2half2(lx, ly);
                    float lxv = sx * gl.x + bl2.x, lyv = sy * gl.y + bl2.y;
                    *reinterpret_cast<__half2*>(O2h + zidx) = __floats2half2_rn(lxv, lyv);
                }
            }
        }
    }
}

// ======================= elementwise / transform kernels ====================
__global__ void ln_kernel(const float* __restrict__ v, const float* __restrict__ g,
                          const float* __restrict__ b, __half* __restrict__ oh)
{
    int row = blockIdx.x;
    const float4* x4 = reinterpret_cast<const float4*>(v + (size_t)row * DIM);
    int t = threadIdx.x;
    float4 a = x4[t];
    float s = a.x + a.y + a.z + a.w;
    __shared__ float red[256];
    red[t] = s; __syncthreads();
    for (int o = 128; o > 0; o >>= 1) { if (t < o) red[t] += red[t+o]; __syncthreads(); }
    float mu = red[0] * (1.f/DIM);
    __syncthreads();
    float dx = a.x-mu, dy = a.y-mu, dz = a.z-mu, dw = a.w-mu;
    red[t] = dx*dx + dy*dy + dz*dz + dw*dw; __syncthreads();
    for (int o = 128; o > 0; o >>= 1) { if (t < o) red[t] += red[t+o]; __syncthreads(); }
    float inv = rsqrtf(red[0] * (1.f/DIM) + 1e-5f);
    float4 g4 = reinterpret_cast<const float4*>(g)[t];
    float4 b4 = reinterpret_cast<const float4*>(b)[t];
    __half2 h0 = __floats2half2_rn(dx*inv*g4.x + b4.x, dy*inv*g4.y + b4.y);
    __half2 h1 = __floats2half2_rn(dz*inv*g4.z + b4.z, dw*inv*g4.w + b4.w);
    reinterpret_cast<uint2*>(oh + (size_t)row * DIM)[t] =
        make_uint2(*reinterpret_cast<uint32_t*>(&h0), *reinterpret_cast<uint32_t*>(&h1));
}

__global__ void bias_kernel(const float* __restrict__ rel_emb, float* __restrict__ bias)
{
    int idx = blockIdx.x * 256 + threadIdx.x;
    int i = idx >> 8, j = idx & 255;
    int n0 = i - j;
    int ret = (n0 < 0) ? 16 : 0;
    int n = n0 < 0 ? -n0 : n0;
    int bucket;
    if (n < 8) bucket = ret + n;
    else {
        int vl = 8 + (int)(logf((float)n * 0.125f) / 2.7725887f * 8.0f);
        if (vl > 15) vl = 15;
        bucket = ret + vl;
    }
    bias[idx] = rel_emb[bucket] * 11.3137085f;
}

__global__ void bcat_kernel(const float* __restrict__ bq, const float* __restrict__ bk,
                            float* __restrict__ o)
{
    int t = threadIdx.x;
    o[t] = (t < QD) ? bq[t] : bk[t - QD];
}

__global__ void cvt4(const float* __restrict__ in, __half* __restrict__ oh)
{
    size_t i = (size_t)blockIdx.x * 256 + threadIdx.x;
    float4 a = reinterpret_cast<const float4*>(in)[i];
    __half2 h0 = __floats2half2_rn(a.x, a.y);
    __half2 h1 = __floats2half2_rn(a.z, a.w);
    reinterpret_cast<uint2*>(oh)[i] =
        make_uint2(*reinterpret_cast<uint32_t*>(&h0), *reinterpret_cast<uint32_t*>(&h1));
}

// transpose fp32 [R, C] -> fp16 [C, R]; ol == nullptr -> h only
__global__ void transcvt(const float* __restrict__ in,
                         __half* __restrict__ oh, __half* __restrict__ ol,
                         int ld_in, int ld_out, long long sIn, long long sOut)
{
    __shared__ float t[32][33];
    in += (long long)blockIdx.z * sIn;
    oh += (long long)blockIdx.z * sOut;
    if (ol) ol += (long long)blockIdx.z * sOut;
    int c0 = blockIdx.x * 32, r0 = blockIdx.y * 32;
    int tx = threadIdx.x, ty = threadIdx.y;
#pragma unroll
    for (int i = 0; i < 4; i++)
        t[ty + i*8][tx] = in[(size_t)(r0 + ty + i*8) * ld_in + c0 + tx];
    __syncthreads();
#pragma unroll
    for (int i = 0; i < 4; i++) {
        float x = t[tx][ty + i*8];
        size_t o = (size_t)(c0 + ty + i*8) * ld_out + r0 + tx;
        __half h, l; split2h(x, h, l);
        oh[o] = h;
        if (ol) ol[o] = l;
    }
}

// pure fp16 transpose [R, C] -> [C, R]
__global__ void trans16(const __half* __restrict__ in, __half* __restrict__ out,
                        int ld_in, int ld_out, long long sIn, long long sOut)
{
    __shared__ __half t[32][34];
    in += (long long)blockIdx.z * sIn;
    out += (long long)blockIdx.z * sOut;
    int c0 = blockIdx.x * 32, r0 = blockIdx.y * 32;
    int tx = threadIdx.x, ty = threadIdx.y;
#pragma unroll
    for (int i = 0; i < 4; i++)
        t[ty + i*8][tx] = in[(size_t)(r0 + ty + i*8) * ld_in + c0 + tx];
    __syncthreads();
#pragma unroll
    for (int i = 0; i < 4; i++)
        out[(size_t)(c0 + ty + i*8) * ld_out + r0 + tx] = t[tx][ty + i*8];
}

// sum 4 split-K partials [4][QD][HID] per batch, transpose -> kvT [HID][QD] (h)
__global__ void kvsum_t(const float* __restrict__ linkv4, __half* __restrict__ kvh)
{
    __shared__ float t[32][33];
    int batch = blockIdx.z;
    const float* base = linkv4 + (size_t)batch * 4 * QD * HID;
    kvh += (size_t)batch * HID * QD;
    int c0 = blockIdx.x * 32, r0 = blockIdx.y * 32;
    int tx = threadIdx.x, ty = threadIdx.y;
#pragma unroll
    for (int i = 0; i < 4; i++) {
        size_t off = (size_t)(r0 + ty + i*8) * HID + c0 + tx;
        float s = base[off] + base[off + (size_t)QD*HID]
                + base[off + (size_t)2*QD*HID] + base[off + (size_t)3*QD*HID];
        t[ty + i*8][tx] = s;
    }
    __syncthreads();
#pragma unroll
    for (int i = 0; i < 4; i++)
        kvh[(size_t)(c0 + ty + i*8) * QD + r0 + tx] = __float2half_rn(t[tx][ty + i*8]);
}

// ======================= host orchestration =================================
static void* symaddr(const void* s) {
    void* p = nullptr;
    cudaGetSymbolAddress(&p, s);
    return p;
}

extern "C" void kernel_launch(void* const* d_in, const int* in_sizes, int n_in,
                              void* d_out, int out_size)
{
    const float* q       = (const float*)d_in[0];
    const float* k       = (const float*)d_in[1];
    const float* v       = (const float*)d_in[2];
    const float* ln_g    = (const float*)d_in[3];
    const float* ln_b    = (const float*)d_in[4];
    const float* w_hid   = (const float*)d_in[5];
    const float* b_hid   = (const float*)d_in[6];
    const float* w_q     = (const float*)d_in[7];
    const float* b_q     = (const float*)d_in[8];
    const float* w_k     = (const float*)d_in[9];
    const float* b_k     = (const float*)d_in[10];
    const float* qs_gamma= (const float*)d_in[11];
    const float* qs_beta = (const float*)d_in[12];
    const float* ks_gamma= (const float*)d_in[13];
    const float* ks_beta = (const float*)d_in[14];
    const float* rel_emb = (const float*)d_in[15];
    const float* w_out   = (const float*)d_in[16];
    const float* b_out   = (const float*)d_in[17];

    float* out = (float*)d_out;

    float* linkv4 = (float*)symaddr(g_linkv4);
    float* biasbuf= (float*)symaddr(g_bias);
    float* bqk    = (float*)symaddr(g_bqk);
    float* attn_scratch = (float*)symaddr(g_attn);

    __half* hidH  = (__half*)symaddr(g_hidH);
    __half* nH    = (__half*)symaddr(g_nH);
    __half* qkIn  = (__half*)symaddr(g_qkIn);
    __half* whTh  = (__half*)symaddr(g_whTh);
    __half* woTh  = (__half*)symaddr(g_woTh);
    __half* wqkTh = (__half*)symaddr(g_wqkTh); __half* wqkTl = (__half*)symaddr(g_wqkTl);
    __half* quadH = (__half*)symaddr(g_quadH); __half* quadL = (__half*)symaddr(g_quadL);
    __half* linH  = (__half*)symaddr(g_linH);
    __half* atH   = (__half*)symaddr(g_atH);
    __half* lkTH  = (__half*)symaddr(g_lkTH);
    __half* vvTh  = (__half*)symaddr(g_vvTh);
    __half* kvTh  = (__half*)symaddr(g_kvTh);
    __half* acH0  = (__half*)symaddr(g_acH0);
    __half* acH   = (__half*)symaddr(g_acH);

    const long long OUT0 = (long long)ROWS * DIM;
    const long long OUT1 = (long long)NGROUP * G * G;
    float* attn = (out_size >= OUT0 + OUT1) ? (out + OUT0) : attn_scratch;

    const long long RQ = (long long)ROWS * QD;

    cudaFuncSetAttribute(hgemm<256,5,1>, cudaFuncAttributeMaxDynamicSharedMemorySize, 110592);
    cudaFuncSetAttribute(hgemm<128,6,2>, cudaFuncAttributeMaxDynamicSharedMemorySize, 110592);
    cudaFuncSetAttribute(hgemm<128,2,3>, cudaFuncAttributeMaxDynamicSharedMemorySize, 147456);
    cudaFuncSetAttribute(hgemm<256,4,1>, cudaFuncAttributeMaxDynamicSharedMemorySize, 110592);
    cudaFuncSetAttribute(hgemm<256,0,1>, cudaFuncAttributeMaxDynamicSharedMemorySize, 110592);
    cudaFuncSetAttribute(hgemm<256,3,1>, cudaFuncAttributeMaxDynamicSharedMemorySize, 110592);

    // ---- multi-stream overlap (event fork/join, capture-legal) ----
    cudaStream_t s0, s1;
    cudaStreamCreateWithFlags(&s0, cudaStreamNonBlocking);
    cudaStreamCreateWithFlags(&s1, cudaStreamNonBlocking);
    cudaEvent_t eStart, e1, eHid, eVvt, eQkp, eLkt, eEnd;
    cudaEventCreateWithFlags(&eStart, cudaEventDisableTiming);
    cudaEventCreateWithFlags(&e1,     cudaEventDisableTiming);
    cudaEventCreateWithFlags(&eHid,   cudaEventDisableTiming);
    cudaEventCreateWithFlags(&eVvt,   cudaEventDisableTiming);
    cudaEventCreateWithFlags(&eQkp,   cudaEventDisableTiming);
    cudaEventCreateWithFlags(&eLkt,   cudaEventDisableTiming);
    cudaEventCreateWithFlags(&eEnd,   cudaEventDisableTiming);

    cudaEventRecord(eStart, 0);
    cudaStreamWaitEvent(s0, eStart, 0);
    cudaStreamWaitEvent(s1, eStart, 0);

    // s1 (side): prologue elementwise, overlapped with hid GEMM
    bias_kernel<<<G*G/256, 256, 0, s1>>>(rel_emb, biasbuf);
    cvt4<<<(int)((size_t)ROWS*DIM/1024), 256, 0, s1>>>(q, qkIn);
    cvt4<<<(int)((size_t)ROWS*DIM/1024), 256, 0, s1>>>(k, qkIn + (size_t)ROWS*DIM);
    transcvt<<<dim3(DIM/32, HID/32, 1), dim3(32,8), 0, s1>>>(w_out, woTh, nullptr, DIM, HID, 0, 0);
    transcvt<<<dim3(QD/32, DIM/32, 1), dim3(32,8), 0, s1>>>(w_q, wqkTh, wqkTl, QD, DIM, 0, 0);
    transcvt<<<dim3(QD/32, DIM/32, 1), dim3(32,8), 0, s1>>>(w_k, wqkTh + QD*DIM, wqkTl + QD*DIM, QD, DIM, 0, 0);
    bcat_kernel<<<1, 2*QD, 0, s1>>>(b_q, b_k, bqk);
    cudaEventRecord(e1, s1);

    // s0 (main): LN + w_hid transpose + hid GEMM
    ln_kernel<<<ROWS, 256, 0, s0>>>(v, ln_g, ln_b, nH);
    transcvt<<<dim3(HID2/32, DIM/32, 1), dim3(32,8), 0, s0>>>(w_hid, whTh, nullptr, HID2, DIM, 0, 0);
    hgemm<256,5,1><<<dim3(HID2/256, ROWS/128, 1), 512, 110592, s0>>>(
        nH, nullptr, whTh, nullptr, nullptr, nullptr, b_hid, 0, nullptr, 0, 0,
        hidH, nullptr, nullptr, nullptr, nullptr, nullptr, nullptr,
        DIM, DIM, DIM, HID2, 0, 0, 0, 0, 1, 0, 1.f);
    cudaEventRecord(eHid, s0);

    // s1: vv^T transpose, overlapped with qkp+sim on s0
    cudaStreamWaitEvent(s1, eHid, 0);
    trans16<<<dim3(HID/32, SEQ/32, BATCH), dim3(32,8), 0, s1>>>(
        hidH, vvTh, HID2, SEQ, (long long)SEQ*HID2, (long long)HID*SEQ);
    cudaEventRecord(eVvt, s1);

    // s0: fused projection + affine (needs s1 prologue)
    cudaStreamWaitEvent(s0, e1, 0);
    hgemm<128,6,2><<<dim3(1, ROWS/128, 2), 256, 110592, s0>>>(
        qkIn, nullptr, wqkTh, wqkTl, nullptr, nullptr, bqk, QD, nullptr, 0, 0,
        quadH, quadL, linH, qs_gamma, qs_beta, ks_gamma, ks_beta,
        DIM, DIM, DIM, QD,
        (long long)ROWS*DIM, 0, (long long)QD*DIM, 0, 1, RQ, 1.f);
    cudaEventRecord(eQkp, s0);

    // s1: lk^T transpose, overlapped with sim/quad on s0
    cudaStreamWaitEvent(s1, eQkp, 0);
    trans16<<<dim3(QD/32, SEQ/32, BATCH), dim3(32,8), 0, s1>>>(
        linH + RQ, lkTH, QD, SEQ, (long long)SEQ*QD, (long long)QD*SEQ);
    cudaEventRecord(eLkt, s1);

    // s0: sim — 3 products (checked output)
    hgemm<128,2,3><<<dim3(G/128, G/128, NGROUP), 256, 147456, s0>>>(
        quadH, quadL, quadH + RQ, quadL + RQ, attn, nullptr, biasbuf, 0, nullptr, 0, 0,
        atH, nullptr, nullptr, nullptr, nullptr, nullptr, nullptr,
        QD, QD, QD, G,
        (long long)G*QD, 0, (long long)G*QD, 0, 1, (long long)G*G, 1.f/G);

    // s0: quad_out = attn @ cv -> fp16 acH0 (needs vvT)
    cudaStreamWaitEvent(s0, eVvt, 0);
    hgemm<256,4,1><<<dim3(HID/256, G/128, NGROUP), 512, 110592, s0>>>(
        atH, nullptr, vvTh, nullptr, nullptr, nullptr, nullptr, 0, nullptr, 0, 0,
        acH0, nullptr, nullptr, nullptr, nullptr, nullptr, nullptr,
        G, G, SEQ, HID,
        (long long)16*G*G, (long long)G*G, (long long)HID*SEQ, (long long)G, 16,
        (long long)G*HID, 1.f);

    // s0: lin_kv split-K 4x (needs lkT)
    cudaStreamWaitEvent(s0, eLkt, 0);
    hgemm<256,0,1><<<dim3(HID/256, 1, 16), 512, 110592, s0>>>(
        lkTH, nullptr, vvTh, nullptr, linkv4, nullptr, nullptr, 0, nullptr, 0, 0,
        nullptr, nullptr, nullptr, nullptr, nullptr, nullptr, nullptr,
        1024, SEQ, SEQ, HID,
        (long long)QD*SEQ, 1024LL, (long long)HID*SEQ, 1024LL, 4,
        (long long)QD*HID, 1.f/SEQ);

    // s0: sum partials + transpose -> kvT (h only)
    kvsum_t<<<dim3(HID/32, QD/32, BATCH), dim3(32,8), 0, s0>>>(linkv4, kvTh);

    // s0: lin_out fused: acH = (lq @ lin_kv + acH0) * gate — 1 product
    hgemm<256,3,1><<<dim3(HID/256, SEQ/128, BATCH), 512, 110592, s0>>>(
        linH, nullptr, kvTh, nullptr, nullptr, acH0, nullptr, 0,
        hidH + HID, HID2, (long long)SEQ*HID2,
        acH, nullptr, nullptr, nullptr, nullptr, nullptr, nullptr,
        QD, QD, QD, HID,
        (long long)SEQ*QD, 0, (long long)HID*QD, 0, 1, (long long)SEQ*HID, 1.f);

    // s0: out = gated @ w_out + b_out
    hgemm<256,0,1><<<dim3(DIM/256, ROWS/128, 1), 512, 110592, s0>>>(
        acH, nullptr, woTh, nullptr, out, nullptr, b_out, 0, nullptr, 0, 0,
        nullptr, nullptr, nullptr, nullptr, nullptr, nullptr, nullptr,
        HID, HID, HID, DIM, 0, 0, 0, 0, 1, 0, 1.f);

    cudaEventRecord(eEnd, s0);
    cudaStreamWaitEvent(0, eEnd, 0);

    cudaEventDestroy(eStart); cudaEventDestroy(e1); cudaEventDestroy(eHid);
    cudaEventDestroy(eVvt);   cudaEventDestroy(eQkp); cudaEventDestroy(eLkt);
    cudaEventDestroy(eEnd);
    cudaStreamDestroy(s0); cudaStreamDestroy(s1);
}

// round 15
// speedup vs baseline: 1.1565x; 1.0111x over previous
#include <cuda_runtime.h>
#include <cuda_fp16.h>
#include <math.h>
#include <stdint.h>

#define G 256
#define BATCH 4
#define SEQ 4096
#define DIM 1024
#define HID 2048      // H
#define HID2 4096     // 2H
#define QD 128
#define ROWS (BATCH*SEQ)   // 16384
#define NGROUP (ROWS/G)    // 64

// ======================= fp32 scratch =======================================
__device__ float g_linkv4[(size_t)16*QD*HID];       // lin_kv split-K partials
__device__ float g_attn[(size_t)NGROUP*G*G];        // fallback if out too small
__device__ float g_bias[G*G];
__device__ float g_bqk[2*QD];                       // concat(b_q, b_k)

// ======================= fp16 planes ========================================
__device__ __align__(16) __half g_hidH[(size_t)ROWS*HID2];                   // hid (vv | gate)
__device__ __align__(16) __half g_nH[(size_t)ROWS*DIM];                      // A: LN(v)
__device__ __align__(16) __half g_qkIn[(size_t)2*ROWS*DIM];                  // A: q | k
__device__ __align__(16) __half g_whTh[(size_t)HID2*DIM];                    // B: w_hid^T (h)
__device__ __align__(16) __half g_woTh[(size_t)DIM*HID];                     // B: w_out^T (h)
__device__ __align__(16) __half g_wqkTh[(size_t)2*QD*DIM], g_wqkTl[(size_t)2*QD*DIM]; // B: wq|wk
__device__ __align__(16) __half g_quadH[(size_t)2*ROWS*QD], g_quadL[(size_t)2*ROWS*QD];
__device__ __align__(16) __half g_linH[(size_t)2*ROWS*QD];                   // lq | lk
__device__ __align__(16) __half g_atH[(size_t)NGROUP*G*G];                   // A: attn
__device__ __align__(16) __half g_lkTH[(size_t)BATCH*QD*SEQ];                // A: lk^T
__device__ __align__(16) __half g_vvTh[(size_t)BATCH*HID*SEQ];               // B: vv^T (h)
__device__ __align__(16) __half g_kvTh[(size_t)BATCH*HID*QD];                // B: lin_kv^T (h)
__device__ __align__(16) __half g_acH0[(size_t)ROWS*HID];                    // quad_out fp16
__device__ __align__(16) __half g_acH[(size_t)ROWS*HID];                     // gated

// ======================= helpers ============================================
__device__ __forceinline__ uint32_t smem_u32(const void* p) {
    uint32_t a;
    asm("{ .reg .u64 t; cvta.to.shared.u64 t, %1; cvt.u32.u64 %0, t; }" : "=r"(a) : "l"(p));
    return a;
}
__device__ __forceinline__ uint32_t lds32(uint32_t a) {
    uint32_t v;
    asm("ld.shared.b32 %0, [%1];" : "=r"(v) : "r"(a));
    return v;
}
__device__ __forceinline__ void split2h(float x, __half& h, __half& l) {
    h = __float2half_rn(x);
    l = __float2half_rn(x - __half2float(h));
}
__device__ __forceinline__ float silu_f(float x) {
    return x / (1.f + __expf(-x));
}

#define MMA_F16(d, a, b) \
    asm volatile("mma.sync.aligned.m16n8k16.row.col.f32.f16.f16.f32 " \
        "{%0,%1,%2,%3}, {%4,%5,%6,%7}, {%8,%9}, {%0,%1,%2,%3};" \
        : "+f"((d)[0]), "+f"((d)[1]), "+f"((d)[2]), "+f"((d)[3]) \
        : "r"((a)[0]), "r"((a)[1]), "r"((a)[2]), "r"((a)[3]), \
          "r"((b)[0]), "r"((b)[1]))

// ======================= fp16 multi-product GEMM ============================
// NP=1: C = Ah@Bh^T; NP=2: += Ah@Bl^T; NP=3: += Al@Bh^T   (fp32 accum)
// EPI: 0  C fp32 = v (+ col bias)
//      2  sim: +bias2d, relu^2 -> fp32 C + fp16 O1h
//      3  O1h = (v + Ch) * gate      (all fp16)
//      4  O1h = v                    (fp16)
//      5  O1h = silu(v + col bias)   (fp16)
//      6  proj+affine (q/k select by z)
#define PITCH 144                     // bytes per smem row (64 fp16 + 8 pad)
#define PLANE_A (128*PITCH)           // 18432 B

template<int RP, int NT>
__device__ __forceinline__ void load_plane(uint32_t sdst, const __half* src,
                                           int row0, int ld, int k0, int tid)
{
#pragma unroll
    for (int i = 0; i < RP*8/NT; i++) {
        int idx = tid + i * NT;
        int r = idx >> 3, seg = idx & 7;
        uint32_t d = sdst + r * PITCH + seg * 16;
        const void* gp = src + (size_t)(row0 + r) * ld + k0 + seg * 8;
        asm volatile("cp.async.cg.shared.global [%0], [%1], 16;" :: "r"(d), "l"(gp));
    }
}

template<int TN, int EPI, int NP>
__global__ void __launch_bounds__(TN == 256 ? 512 : 256, 1) hgemm(
    const __half* __restrict__ Ah, const __half* __restrict__ Al,
    const __half* __restrict__ Bh, const __half* __restrict__ Bl,
    float* __restrict__ C, const __half* __restrict__ Ch,
    const float* __restrict__ bias, int biasStride,
    const __half* __restrict__ gate, int ldg, long long sG,
    __half* __restrict__ O1h, __half* __restrict__ O1l, __half* __restrict__ O2h,
    const float* __restrict__ gbQ, const float* __restrict__ gbQb,
    const float* __restrict__ gbK, const float* __restrict__ gbKb,
    int K, int lda, int ldb, int ldc,
    long long sA, long long sAi, long long sBo, long long sBi, int zdiv,
    long long sC, float alpha)
{
    constexpr int NT = (TN == 256) ? 512 : 256;
    constexpr int NA = (NP == 3) ? 2 : 1;
    constexpr int NB = (NP >= 2) ? 2 : 1;
    constexpr int PLANE_B = TN * PITCH;
    constexpr int B_OFF = NA * PLANE_A;
    constexpr int STG = NA * PLANE_A + NB * PLANE_B;

    extern __shared__ char smem[];
    const int z = blockIdx.z;
    const int zo = z / zdiv, zi = z - zo * zdiv;
    long long ao = (long long)zo * sA + (long long)zi * sAi;
    long long bo = (long long)zo * sBo + (long long)zi * sBi;
    Ah += ao;
    if (NA == 2) Al += ao;
    Bh += bo;
    if (NB == 2) Bl += bo;
    if (C) C += (long long)z * sC;
    if (bias) bias += (long long)z * biasStride;
    const int bm = blockIdx.y * 128, bn = blockIdx.x * TN;

    const uint32_t sb = smem_u32(smem);
    const int tid = threadIdx.x;
    const int lane = tid & 31, wid = tid >> 5;
    const int warp_m = wid & 3, warp_n = wid >> 2;    // 4 x (TN/64) warps
    const int gr = lane >> 2, tq = lane & 3;

    float acc[2][8][4];
#pragma unroll
    for (int mt = 0; mt < 2; mt++)
#pragma unroll
        for (int nt = 0; nt < 8; nt++)
#pragma unroll
            for (int i = 0; i < 4; i++) acc[mt][nt][i] = 0.f;

    const int nchunks = K >> 6;

    load_plane<128, NT>(sb, Ah, bm, lda, 0, tid);
    if (NA == 2) load_plane<128, NT>(sb + PLANE_A, Al, bm, lda, 0, tid);
    load_plane<TN, NT>(sb + B_OFF, Bh, bn, ldb, 0, tid);
    if (NB == 2) load_plane<TN, NT>(sb + B_OFF + PLANE_B, Bl, bn, ldb, 0, tid);
    asm volatile("cp.async.commit_group;");

    for (int c = 0; c < nchunks; ++c) {
        if (c + 1 < nchunks) {
            uint32_t st = sb + ((c + 1) & 1) * STG;
            int k0 = (c + 1) << 6;
            load_plane<128, NT>(st, Ah, bm, lda, k0, tid);
            if (NA == 2) load_plane<128, NT>(st + PLANE_A, Al, bm, lda, k0, tid);
            load_plane<TN, NT>(st + B_OFF, Bh, bn, ldb, k0, tid);
            if (NB == 2) load_plane<TN, NT>(st + B_OFF + PLANE_B, Bl, bn, ldb, k0, tid);
            asm volatile("cp.async.commit_group;");
            asm volatile("cp.async.wait_group %0;" :: "n"(1));
        } else {
            asm volatile("cp.async.wait_group %0;" :: "n"(0));
        }
        __syncthreads();

        const uint32_t stg = sb + (c & 1) * STG;
#pragma unroll
        for (int kk = 0; kk < 4; kk++) {
            const int koff = kk * 32;
            uint32_t a_h[2][4], a_l[2][4];
#pragma unroll
            for (int mt = 0; mt < 2; mt++) {
                uint32_t ro = stg + (warp_m*32 + mt*16 + gr) * PITCH + koff + tq*4;
                a_h[mt][0] = lds32(ro);
                a_h[mt][1] = lds32(ro + 8*PITCH);
                a_h[mt][2] = lds32(ro + 16);
                a_h[mt][3] = lds32(ro + 8*PITCH + 16);
                if (NA == 2) {
                    uint32_t rl = ro + PLANE_A;
                    a_l[mt][0] = lds32(rl);
                    a_l[mt][1] = lds32(rl + 8*PITCH);
                    a_l[mt][2] = lds32(rl + 16);
                    a_l[mt][3] = lds32(rl + 8*PITCH + 16);
                }
            }
#pragma unroll
            for (int nt = 0; nt < 8; nt++) {
                uint32_t ro = stg + B_OFF + (warp_n*64 + nt*8 + gr) * PITCH + koff + tq*4;
                uint32_t b_h[2], b_l[2];
                b_h[0] = lds32(ro);
                b_h[1] = lds32(ro + 16);
                if (NB == 2) {
                    b_l[0] = lds32(ro + PLANE_B);
                    b_l[1] = lds32(ro + PLANE_B + 16);
                }
#pragma unroll
                for (int mt = 0; mt < 2; mt++) {
                    MMA_F16(acc[mt][nt], a_h[mt], b_h);
                    if (NP >= 2) MMA_F16(acc[mt][nt], a_h[mt], b_l);
                    if (NP == 3) MMA_F16(acc[mt][nt], a_l[mt], b_h);
                }
            }
        }
        __syncthreads();
    }

    // epilogue
    const float* gbG = (EPI == 6) ? (z ? gbK : gbQ) : nullptr;
    const float* gbB = (EPI == 6) ? (z ? gbKb : gbQb) : nullptr;
#pragma unroll
    for (int mt = 0; mt < 2; mt++) {
        const int row0 = bm + warp_m*32 + mt*16 + gr;
#pragma unroll
        for (int nt = 0; nt < 8; nt++) {
            const int col = bn + warp_n*64 + nt*8 + tq*2;
            float2 bb = make_float2(0.f, 0.f);
            if ((EPI == 0 || EPI == 5 || EPI == 6) && bias)
                bb = *reinterpret_cast<const float2*>(bias + col);
#pragma unroll
            for (int h = 0; h < 2; h++) {
                const int row = row0 + h*8;
                float vx = acc[mt][nt][h*2+0] * alpha;
                float vy = acc[mt][nt][h*2+1] * alpha;
                const size_t idx = (size_t)row * ldc + col;
                const size_t zidx = (long long)z * sC + idx;
                if (EPI == 0) {
                    *reinterpret_cast<float2*>(C + idx) = make_float2(vx + bb.x, vy + bb.y);
                } else if (EPI == 2) {
                    float2 b2 = *reinterpret_cast<const float2*>(bias + (size_t)row * G + col);
                    vx += b2.x; vy += b2.y;
                    vx = fmaxf(vx, 0.f); vy = fmaxf(vy, 0.f);
                    vx *= vx; vy *= vy;
                    *reinterpret_cast<float2*>(C + idx) = make_float2(vx, vy);
                    *reinterpret_cast<__half2*>(O1h + zidx) = __floats2half2_rn(vx, vy);
                } else if (EPI == 3) {
                    __half2 o2 = *reinterpret_cast<const __half2*>(Ch + zidx);
                    float2 o = __half22float2(o2);
                    __half2 g2h = *reinterpret_cast<const __half2*>(
                        gate + (long long)z * sG + (size_t)row * ldg + col);
                    float2 g2 = __half22float2(g2h);
                    vx = (vx + o.x) * g2.x;
                    vy = (vy + o.y) * g2.y;
                    *reinterpret_cast<__half2*>(O1h + zidx) = __floats2half2_rn(vx, vy);
                } else if (EPI == 4) {
                    *reinterpret_cast<__half2*>(O1h + zidx) = __floats2half2_rn(vx, vy);
                } else if (EPI == 5) {
                    vx = silu_f(vx + bb.x);
                    vy = silu_f(vy + bb.y);
                    *reinterpret_cast<__half2*>(O1h + idx) = __floats2half2_rn(vx, vy);
                } else if (EPI == 6) {
                    float sx = silu_f(vx + bb.x);
                    float sy = silu_f(vy + bb.y);
                    float2 gq = *reinterpret_cast<const float2*>(gbG + col);
                    float2 bq2 = *reinterpret_cast<const float2*>(gbB + col);
                    float2 gl = *reinterpret_cast<const float2*>(gbG + QD + col);
                    float2 bl2 = *reinterpret_cast<const float2*>(gbB + QD + col);
                    float qx = sx * gq.x + bq2.x, qy = sy * gq.y + bq2.y;
                    __half hx, lx, hy, ly;
                    split2h(qx, hx, lx); split2h(qy, hy, ly);
                    *reinterpret_cast<__half2*>(O1h + zidx) = __halves2half2(hx, hy);
                    *reinterpret_cast<__half2*>(O1l + zidx) = __halves2half2(lx, ly);
                    float lxv = sx * gl.x + bl2.x, lyv = sy * gl.y + bl2.y;
                    *reinterpret_cast<__half2*>(O2h + zidx) = __floats2half2_rn(lxv, lyv);
                }
            }
        }
    }
}

// ======================= elementwise / transform kernels ====================
__global__ void ln_kernel(const float* __restrict__ v, const float* __restrict__ g,
                          const float* __restrict__ b, __half* __restrict__ oh)
{
    int row = blockIdx.x;
    const float4* x4 = reinterpret_cast<const float4*>(v + (size_t)row * DIM);
    int t = threadIdx.x;
    float4 a = x4[t];
    float s = a.x + a.y + a.z + a.w;
    __shared__ float red[256];
    red[t] = s; __syncthreads();
    for (int o = 128; o > 0; o >>= 1) { if (t < o) red[t] += red[t+o]; __syncthreads(); }
    float mu = red[0] * (1.f/DIM);
    __syncthreads();
    float dx = a.x-mu, dy = a.y-mu, dz = a.z-mu, dw = a.w-mu;
    red[t] = dx*dx + dy*dy + dz*dz + dw*dw; __syncthreads();
    for (int o = 128; o > 0; o >>= 1) { if (t < o) red[t] += red[t+o]; __syncthreads(); }
    float inv = rsqrtf(red[0] * (1.f/DIM) + 1e-5f);
    float4 g4 = reinterpret_cast<const float4*>(g)[t];
    float4 b4 = reinterpret_cast<const float4*>(b)[t];
    __half2 h0 = __floats2half2_rn(dx*inv*g4.x + b4.x, dy*inv*g4.y + b4.y);
    __half2 h1 = __floats2half2_rn(dz*inv*g4.z + b4.z, dw*inv*g4.w + b4.w);
    reinterpret_cast<uint2*>(oh + (size_t)row * DIM)[t] =
        make_uint2(*reinterpret_cast<uint32_t*>(&h0), *reinterpret_cast<uint32_t*>(&h1));
}

__global__ void bias_kernel(const float* __restrict__ rel_emb, float* __restrict__ bias)
{
    int idx = blockIdx.x * 256 + threadIdx.x;
    int i = idx >> 8, j = idx & 255;
    int n0 = i - j;
    int ret = (n0 < 0) ? 16 : 0;
    int n = n0 < 0 ? -n0 : n0;
    int bucket;
    if (n < 8) bucket = ret + n;
    else {
        int vl = 8 + (int)(logf((float)n * 0.125f) / 2.7725887f * 8.0f);
        if (vl > 15) vl = 15;
        bucket = ret + vl;
    }
    bias[idx] = rel_emb[bucket] * 11.3137085f;
}

__global__ void bcat_kernel(const float* __restrict__ bq, const float* __restrict__ bk,
                            float* __restrict__ o)
{
    int t = threadIdx.x;
    o[t] = (t < QD) ? bq[t] : bk[t - QD];
}

__global__ void cvt4(const float* __restrict__ in, __half* __restrict__ oh)
{
    size_t i = (size_t)blockIdx.x * 256 + threadIdx.x;
    float4 a = reinterpret_cast<const float4*>(in)[i];
    __half2 h0 = __floats2half2_rn(a.x, a.y);
    __half2 h1 = __floats2half2_rn(a.z, a.w);
    reinterpret_cast<uint2*>(oh)[i] =
        make_uint2(*reinterpret_cast<uint32_t*>(&h0), *reinterpret_cast<uint32_t*>(&h1));
}

// transpose fp32 [R, C] -> fp16 [C, R]; ol == nullptr -> h only
__global__ void transcvt(const float* __restrict__ in,
                         __half* __restrict__ oh, __half* __restrict__ ol,
                         int ld_in, int ld_out, long long sIn, long long sOut)
{
    __shared__ float t[32][33];
    in += (long long)blockIdx.z * sIn;
    oh += (long long)blockIdx.z * sOut;
    if (ol) ol += (long long)blockIdx.z * sOut;
    int c0 = blockIdx.x * 32, r0 = blockIdx.y * 32;
    int tx = threadIdx.x, ty = threadIdx.y;
#pragma unroll
    for (int i = 0; i < 4; i++)
        t[ty + i*8][tx] = in[(size_t)(r0 + ty + i*8) * ld_in + c0 + tx];
    __syncthreads();
#pragma unroll
    for (int i = 0; i < 4; i++) {
        float x = t[tx][ty + i*8];
        size_t o = (size_t)(c0 + ty + i*8) * ld_out + r0 + tx;
        __half h, l; split2h(x, h, l);
        oh[o] = h;
        if (ol) ol[o] = l;
    }
}

// pure fp16 transpose [R, C] -> [C, R]
__global__ void trans16(const __half* __restrict__ in, __half* __restrict__ out,
                        int ld_in, int ld_out, long long sIn, long long sOut)
{
    __shared__ __half t[32][34];
    in += (long long)blockIdx.z * sIn;
    out += (long long)blockIdx.z * sOut;
    int c0 = blockIdx.x * 32, r0 = blockIdx.y * 32;
    int tx = threadIdx.x, ty = threadIdx.y;
#pragma unroll
    for (int i = 0; i < 4; i++)
        t[ty + i*8][tx] = in[(size_t)(r0 + ty + i*8) * ld_in + c0 + tx];
    __syncthreads();
#pragma unroll
    for (int i = 0; i < 4; i++)
        out[(size_t)(c0 + ty + i*8) * ld_out + r0 + tx] = t[tx][ty + i*8];
}

// sum 4 split-K partials [4][QD][HID] per batch, transpose -> kvT [HID][QD] (h)
__global__ void kvsum_t(const float* __restrict__ linkv4, __half* __restrict__ kvh)
{
    __shared__ float t[32][33];
    int batch = blockIdx.z;
    const float* base = linkv4 + (size_t)batch * 4 * QD * HID;
    kvh += (size_t)batch * HID * QD;
    int c0 = blockIdx.x * 32, r0 = blockIdx.y * 32;
    int tx = threadIdx.x, ty = threadIdx.y;
#pragma unroll
    for (int i = 0; i < 4; i++) {
        size_t off = (size_t)(r0 + ty + i*8) * HID + c0 + tx;
        float s = base[off] + base[off + (size_t)QD*HID]
                + base[off + (size_t)2*QD*HID] + base[off + (size_t)3*QD*HID];
        t[ty + i*8][tx] = s;
    }
    __syncthreads();
#pragma unroll
    for (int i = 0; i < 4; i++)
        kvh[(size_t)(c0 + ty + i*8) * QD + r0 + tx] = __float2half_rn(t[tx][ty + i*8]);
}

// ======================= host orchestration =================================
static void* symaddr(const void* s) {
    void* p = nullptr;
    cudaGetSymbolAddress(&p, s);
    return p;
}

extern "C" void kernel_launch(void* const* d_in, const int* in_sizes, int n_in,
                              void* d_out, int out_size)
{
    const float* q       = (const float*)d_in[0];
    const float* k       = (const float*)d_in[1];
    const float* v       = (const float*)d_in[2];
    const float* ln_g    = (const float*)d_in[3];
    const float* ln_b    = (const float*)d_in[4];
    const float* w_hid   = (const float*)d_in[5];
    const float* b_hid   = (const float*)d_in[6];
    const float* w_q     = (const float*)d_in[7];
    const float* b_q     = (const float*)d_in[8];
    const float* w_k     = (const float*)d_in[9];
    const float* b_k     = (const float*)d_in[10];
    const float* qs_gamma= (const float*)d_in[11];
    const float* qs_beta = (const float*)d_in[12];
    const float* ks_gamma= (const float*)d_in[13];
    const float* ks_beta = (const float*)d_in[14];
    const float* rel_emb = (const float*)d_in[15];
    const float* w_out   = (const float*)d_in[16];
    const float* b_out   = (const float*)d_in[17];

    float* out = (float*)d_out;

    float* linkv4 = (float*)symaddr(g_linkv4);
    float* biasbuf= (float*)symaddr(g_bias);
    float* bqk    = (float*)symaddr(g_bqk);
    float* attn_scratch = (float*)symaddr(g_attn);

    __half* hidH  = (__half*)symaddr(g_hidH);
    __half* nH    = (__half*)symaddr(g_nH);
    __half* qkIn  = (__half*)symaddr(g_qkIn);
    __half* whTh  = (__half*)symaddr(g_whTh);
    __half* woTh  = (__half*)symaddr(g_woTh);
    __half* wqkTh = (__half*)symaddr(g_wqkTh); __half* wqkTl = (__half*)symaddr(g_wqkTl);
    __half* quadH = (__half*)symaddr(g_quadH); __half* quadL = (__half*)symaddr(g_quadL);
    __half* linH  = (__half*)symaddr(g_linH);
    __half* atH   = (__half*)symaddr(g_atH);
    __half* lkTH  = (__half*)symaddr(g_lkTH);
    __half* vvTh  = (__half*)symaddr(g_vvTh);
    __half* kvTh  = (__half*)symaddr(g_kvTh);
    __half* acH0  = (__half*)symaddr(g_acH0);
    __half* acH   = (__half*)symaddr(g_acH);

    const long long OUT0 = (long long)ROWS * DIM;
    const long long OUT1 = (long long)NGROUP * G * G;
    float* attn = (out_size >= OUT0 + OUT1) ? (out + OUT0) : attn_scratch;

    const long long RQ = (long long)ROWS * QD;

    cudaFuncSetAttribute(hgemm<256,5,1>, cudaFuncAttributeMaxDynamicSharedMemorySize, 110592);
    cudaFuncSetAttribute(hgemm<128,6,2>, cudaFuncAttributeMaxDynamicSharedMemorySize, 110592);
    cudaFuncSetAttribute(hgemm<128,2,3>, cudaFuncAttributeMaxDynamicSharedMemorySize, 147456);
    cudaFuncSetAttribute(hgemm<256,4,1>, cudaFuncAttributeMaxDynamicSharedMemorySize, 110592);
    cudaFuncSetAttribute(hgemm<256,0,1>, cudaFuncAttributeMaxDynamicSharedMemorySize, 110592);
    cudaFuncSetAttribute(hgemm<256,3,1>, cudaFuncAttributeMaxDynamicSharedMemorySize, 110592);

    // ---- dual-chain dataflow schedule (event fork/join, capture-legal) ----
    cudaStream_t s0, s1;
    cudaStreamCreateWithFlags(&s0, cudaStreamNonBlocking);
    cudaStreamCreateWithFlags(&s1, cudaStreamNonBlocking);
    cudaEvent_t eStart, eVvt, eSim, eKv, eEnd;
    cudaEventCreateWithFlags(&eStart, cudaEventDisableTiming);
    cudaEventCreateWithFlags(&eVvt,   cudaEventDisableTiming);
    cudaEventCreateWithFlags(&eSim,   cudaEventDisableTiming);
    cudaEventCreateWithFlags(&eKv,    cudaEventDisableTiming);
    cudaEventCreateWithFlags(&eEnd,   cudaEventDisableTiming);

    cudaEventRecord(eStart, 0);
    cudaStreamWaitEvent(s0, eStart, 0);
    cudaStreamWaitEvent(s1, eStart, 0);

    // ===== chain s1: q/k projection -> sim -> lin_kv =====
    bias_kernel<<<G*G/256, 256, 0, s1>>>(rel_emb, biasbuf);
    cvt4<<<(int)((size_t)ROWS*DIM/1024), 256, 0, s1>>>(q, qkIn);
    cvt4<<<(int)((size_t)ROWS*DIM/1024), 256, 0, s1>>>(k, qkIn + (size_t)ROWS*DIM);
    transcvt<<<dim3(QD/32, DIM/32, 1), dim3(32,8), 0, s1>>>(w_q, wqkTh, wqkTl, QD, DIM, 0, 0);
    transcvt<<<dim3(QD/32, DIM/32, 1), dim3(32,8), 0, s1>>>(w_k, wqkTh + QD*DIM, wqkTl + QD*DIM, QD, DIM, 0, 0);
    bcat_kernel<<<1, 2*QD, 0, s1>>>(b_q, b_k, bqk);
    transcvt<<<dim3(DIM/32, HID/32, 1), dim3(32,8), 0, s1>>>(w_out, woTh, nullptr, DIM, HID, 0, 0);

    // fused projection + affine (z=0: q -> qq,lq; z=1: k -> qk,lk), 2 products
    hgemm<128,6,2><<<dim3(1, ROWS/128, 2), 256, 110592, s1>>>(
        qkIn, nullptr, wqkTh, wqkTl, nullptr, nullptr, bqk, QD, nullptr, 0, 0,
        quadH, quadL, linH, qs_gamma, qs_beta, ks_gamma, ks_beta,
        DIM, DIM, DIM, QD,
        (long long)ROWS*DIM, 0, (long long)QD*DIM, 0, 1, RQ, 1.f);

    // lk^T transpose
    trans16<<<dim3(QD/32, SEQ/32, BATCH), dim3(32,8), 0, s1>>>(
        linH + RQ, lkTH, QD, SEQ, (long long)SEQ*QD, (long long)QD*SEQ);

    // sim: attn = relu(qq@qk^T / G + bias)^2 — 3 products (checked output)
    hgemm<128,2,3><<<dim3(G/128, G/128, NGROUP), 256, 147456, s1>>>(
        quadH, quadL, quadH + RQ, quadL + RQ, attn, nullptr, biasbuf, 0, nullptr, 0, 0,
        atH, nullptr, nullptr, nullptr, nullptr, nullptr, nullptr,
        QD, QD, QD, G,
        (long long)G*QD, 0, (long long)G*QD, 0, 1, (long long)G*G, 1.f/G);
    cudaEventRecord(eSim, s1);

    // lin_kv split-K (needs vvT from s0)
    cudaStreamWaitEvent(s1, eVvt, 0);
    hgemm<256,0,1><<<dim3(HID/256, 1, 16), 512, 110592, s1>>>(
        lkTH, nullptr, vvTh, nullptr, linkv4, nullptr, nullptr, 0, nullptr, 0, 0,
        nullptr, nullptr, nullptr, nullptr, nullptr, nullptr, nullptr,
        1024, SEQ, SEQ, HID,
        (long long)QD*SEQ, 1024LL, (long long)HID*SEQ, 1024LL, 4,
        (long long)QD*HID, 1.f/SEQ);
    kvsum_t<<<dim3(HID/32, QD/32, BATCH), dim3(32,8), 0, s1>>>(linkv4, kvTh);
    cudaEventRecord(eKv, s1);

    // ===== chain s0: hid -> vvT -> quad -> lin_out -> out =====
    ln_kernel<<<ROWS, 256, 0, s0>>>(v, ln_g, ln_b, nH);
    transcvt<<<dim3(HID2/32, DIM/32, 1), dim3(32,8), 0, s0>>>(w_hid, whTh, nullptr, HID2, DIM, 0, 0);
    hgemm<256,5,1><<<dim3(HID2/256, ROWS/128, 1), 512, 110592, s0>>>(
        nH, nullptr, whTh, nullptr, nullptr, nullptr, b_hid, 0, nullptr, 0, 0,
        hidH, nullptr, nullptr, nullptr, nullptr, nullptr, nullptr,
        DIM, DIM, DIM, HID2, 0, 0, 0, 0, 1, 0, 1.f);

    // vv^T transpose
    trans16<<<dim3(HID/32, SEQ/32, BATCH), dim3(32,8), 0, s0>>>(
        hidH, vvTh, HID2, SEQ, (long long)SEQ*HID2, (long long)HID*SEQ);
    cudaEventRecord(eVvt, s0);

    // quad_out = attn @ cv -> fp16 acH0 (needs sim from s1)
    cudaStreamWaitEvent(s0, eSim, 0);
    hgemm<256,4,1><<<dim3(HID/256, G/128, NGROUP), 512, 110592, s0>>>(
        atH, nullptr, vvTh, nullptr, nullptr, nullptr, nullptr, 0, nullptr, 0, 0,
        acH0, nullptr, nullptr, nullptr, nullptr, nullptr, nullptr,
        G, G, SEQ, HID,
        (long long)16*G*G, (long long)G*G, (long long)HID*SEQ, (long long)G, 16,
        (long long)G*HID, 1.f);

    // lin_out fused: acH = (lq @ lin_kv + acH0) * gate (needs kvT from s1)
    cudaStreamWaitEvent(s0, eKv, 0);
    hgemm<256,3,1><<<dim3(HID/256, SEQ/128, BATCH), 512, 110592, s0>>>(
        linH, nullptr, kvTh, nullptr, nullptr, acH0, nullptr, 0,
        hidH + HID, HID2, (long long)SEQ*HID2,
        acH, nullptr, nullptr, nullptr, nullptr, nullptr, nullptr,
        QD, QD, QD, HID,
        (long long)SEQ*QD, 0, (long long)HID*QD, 0, 1, (long long)SEQ*HID, 1.f);

    // out = gated @ w_out + b_out
    hgemm<256,0,1><<<dim3(DIM/256, ROWS/128, 1), 512, 110592, s0>>>(
        acH, nullptr, woTh, nullptr, out, nullptr, b_out, 0, nullptr, 0, 0,
        nullptr, nullptr, nullptr, nullptr, nullptr, nullptr, nullptr,
        HID, HID, HID, DIM, 0, 0, 0, 0, 1, 0, 1.f);

    cudaEventRecord(eEnd, s0);
    cudaStreamWaitEvent(0, eEnd, 0);

    cudaEventDestroy(eStart); cudaEventDestroy(eVvt); cudaEventDestroy(eSim);
    cudaEventDestroy(eKv);    cudaEventDestroy(eEnd);
    cudaStreamDestroy(s0); cudaStreamDestroy(s1);
}